// round 3
// baseline (speedup 1.0000x reference)
#include <cuda_runtime.h>
#include <float.h>

// ---------------------------------------------------------------------------
// PointSIFT select_cube + group: spatial-hash (counting sort on a 10^3 grid,
// cell size == radius) -> per-octant nearest neighbor -> gather.
//
// Output layout (float32, concatenated in reference return order):
//   [0 .. BN*8*3)                 grouped_xyz   [B,N,8,3]
//   [BN*8*3 .. +BN*8*(3+C))       grouped_points[B,N,8,3+C]
//   [.. +BN*8)                    idx (int32 cast to float) [B,N,8]
// ---------------------------------------------------------------------------

#define GRIDR   10
#define NCELL   (GRIDR*GRIDR*GRIDR)   // 1000
#define BMAX    2
#define NMAX    4096
#define PRADIUS 0.1f

// Scratch (allocation-free: __device__ globals)
__device__ int    g_count [BMAX * NCELL];
__device__ int    g_start [BMAX * (NCELL + 1)];
__device__ int    g_cursor[BMAX * NCELL];
__device__ float4 g_sorted[BMAX * NMAX];          // x,y,z, w=bitcast(orig index)
__device__ int    g_bidx  [BMAX * NMAX * 8];      // winning neighbor per octant

__device__ __forceinline__ int cell_of(float x, float y, float z) {
    int cx = (int)(x * 10.0f); cx = min(max(cx, 0), GRIDR - 1);
    int cy = (int)(y * 10.0f); cy = min(max(cy, 0), GRIDR - 1);
    int cz = (int)(z * 10.0f); cz = min(max(cz, 0), GRIDR - 1);
    return (cx * GRIDR + cy) * GRIDR + cz;
}

__global__ void k_zero(int n) {
    int t = blockIdx.x * blockDim.x + threadIdx.x;
    if (t < n) g_count[t] = 0;
}

__global__ void k_hist(const float* __restrict__ xyz, int B, int N) {
    int t = blockIdx.x * blockDim.x + threadIdx.x;
    if (t >= B * N) return;
    int b = t / N;
    float x = xyz[3 * t + 0], y = xyz[3 * t + 1], z = xyz[3 * t + 2];
    atomicAdd(&g_count[b * NCELL + cell_of(x, y, z)], 1);
}

// One block per batch; 1024-wide Hillis-Steele inclusive scan over 1000 cells.
__global__ void k_scan() {
    __shared__ int s[1024];
    int b = blockIdx.x;
    int tid = threadIdx.x;
    int v = (tid < NCELL) ? g_count[b * NCELL + tid] : 0;
    s[tid] = v;
    __syncthreads();
    #pragma unroll
    for (int off = 1; off < 1024; off <<= 1) {
        int t = (tid >= off) ? s[tid - off] : 0;
        __syncthreads();
        s[tid] += t;
        __syncthreads();
    }
    if (tid < NCELL) {
        int excl = s[tid] - v;
        g_start [b * (NCELL + 1) + tid] = excl;
        g_cursor[b * NCELL + tid]       = excl;
        if (tid == NCELL - 1)
            g_start[b * (NCELL + 1) + NCELL] = s[tid];
    }
}

__global__ void k_scatter(const float* __restrict__ xyz, int B, int N) {
    int t = blockIdx.x * blockDim.x + threadIdx.x;
    if (t >= B * N) return;
    int b = t / N;
    int i = t - b * N;
    float x = xyz[3 * t + 0], y = xyz[3 * t + 1], z = xyz[3 * t + 2];
    int c = cell_of(x, y, z);
    int pos = atomicAdd(&g_cursor[b * NCELL + c], 1);
    g_sorted[b * NMAX + pos] = make_float4(x, y, z, __int_as_float(i));
}

// One thread per query point: scan <=27 neighbor cells, keep per-octant
// nearest with argmin-first (smallest j) tie-break. Dist computed WITHOUT
// FMA contraction to match the reference's unfused fp32 evaluation.
__global__ void k_query(const float* __restrict__ xyz,
                        float* __restrict__ out_idx_f,
                        int B, int N) {
    int t = blockIdx.x * blockDim.x + threadIdx.x;
    if (t >= B * N) return;
    int b = t / N;
    int i = t - b * N;
    const float* xb = xyz + (size_t)b * N * 3;
    float xi = xb[3 * i + 0], yi = xb[3 * i + 1], zi = xb[3 * i + 2];

    float best[8];
    int   bj[8];
    #pragma unroll
    for (int o = 0; o < 8; o++) { best[o] = FLT_MAX; bj[o] = i; }

    int cx = min(max((int)(xi * 10.0f), 0), GRIDR - 1);
    int cy = min(max((int)(yi * 10.0f), 0), GRIDR - 1);
    int cz = min(max((int)(zi * 10.0f), 0), GRIDR - 1);
    int ax0 = max(cx - 1, 0), ax1 = min(cx + 1, GRIDR - 1);
    int ay0 = max(cy - 1, 0), ay1 = min(cy + 1, GRIDR - 1);
    int az0 = max(cz - 1, 0), az1 = min(cz + 1, GRIDR - 1);

    const int sbase = b * (NCELL + 1);
    for (int ax = ax0; ax <= ax1; ++ax) {
        for (int ay = ay0; ay <= ay1; ++ay) {
            int rowc = (ax * GRIDR + ay) * GRIDR;
            for (int az = az0; az <= az1; ++az) {
                int cell = rowc + az;
                int s0 = g_start[sbase + cell];
                int e0 = g_start[sbase + cell + 1];
                for (int k = s0; k < e0; ++k) {
                    float4 p = g_sorted[b * NMAX + k];
                    float dx = p.x - xi;
                    float dy = p.y - yi;
                    float dz = p.z - zi;
                    if (fabsf(dx) < PRADIUS && fabsf(dy) < PRADIUS &&
                        fabsf(dz) < PRADIUS) {
                        int j = __float_as_int(p.w);
                        float d = __fadd_rn(
                            __fadd_rn(__fmul_rn(dx, dx), __fmul_rn(dy, dy)),
                            __fmul_rn(dz, dz));
                        int oct = ((dx > 0.0f) ? 4 : 0) |
                                  ((dy > 0.0f) ? 2 : 0) |
                                  ((dz > 0.0f) ? 1 : 0);
                        #pragma unroll
                        for (int o = 0; o < 8; o++) {
                            if (oct == o) {
                                if (d < best[o] ||
                                    (d == best[o] && j < bj[o])) {
                                    best[o] = d;
                                    bj[o]   = j;
                                }
                            }
                        }
                    }
                }
            }
        }
    }

    #pragma unroll
    for (int o = 0; o < 8; o++) {
        g_bidx[(size_t)t * 8 + o]    = bj[o];
        out_idx_f[(size_t)t * 8 + o] = (float)bj[o];
    }
}

// One warp per (b,i,o) group: writes 3 centered coords + C gathered features.
__global__ void k_gather(const float* __restrict__ xyz,
                         const float* __restrict__ pts,
                         float* __restrict__ gxyz,
                         float* __restrict__ gp,
                         int B, int N, int C) {
    int warps_per_blk = blockDim.x >> 5;
    int g = blockIdx.x * warps_per_blk + (threadIdx.x >> 5);
    int total = B * N * 8;
    if (g >= total) return;
    int lane = threadIdx.x & 31;

    int jj  = g_bidx[g];
    int b   = g / (N * 8);
    int loc = g - b * N * 8;
    int i   = loc >> 3;

    const float* xb = xyz + (size_t)b * N * 3;
    const float* pb = pts + (size_t)b * N * C;
    int F = 3 + C;

    for (int c = lane; c < F; c += 32) {
        float v;
        if (c < 3) v = xb[jj * 3 + c] - xb[i * 3 + c];
        else       v = pb[(size_t)jj * C + (c - 3)];
        gp[(size_t)g * F + c] = v;
        if (c < 3) gxyz[(size_t)g * 3 + c] = v;
    }
}

extern "C" void kernel_launch(void* const* d_in, const int* in_sizes, int n_in,
                              void* d_out, int out_size) {
    const float* xyz = (const float*)d_in[0];
    const float* pts = (const float*)d_in[1];
    float* out = (float*)d_out;

    int BN = in_sizes[0] / 3;       // B*N = 8192
    int B  = 2;
    int N  = BN / B;                // 4096
    int C  = in_sizes[1] / BN;      // 64

    size_t nG = (size_t)BN * 8;
    float* gxyz  = out;
    float* gp    = out + nG * 3;
    float* idx_f = out + nG * 3 + nG * (size_t)(3 + C);

    k_zero   <<<(B * NCELL + 255) / 256, 256>>>(B * NCELL);
    k_hist   <<<(BN + 255) / 256, 256>>>(xyz, B, N);
    k_scan   <<<B, 1024>>>();
    k_scatter<<<(BN + 255) / 256, 256>>>(xyz, B, N);
    k_query  <<<(BN + 127) / 128, 128>>>(xyz, idx_f, B, N);
    k_gather <<<(int)((nG + 7) / 8), 256>>>(xyz, pts, gxyz, gp, B, N, C);
}

// round 4
// speedup vs baseline: 2.4102x; 2.4102x over previous
#include <cuda_runtime.h>
#include <float.h>

// ---------------------------------------------------------------------------
// PointSIFT select_cube + group.
// R3: warp-per-query octant search (was thread-per-query, latency-bound).
// Spatial hash: counting sort on 10^3 grid (cell == radius). The 27-cell
// neighborhood collapses to 9 contiguous spans in the sorted array (z cells
// are adjacent), scanned lane-strided; per-octant argmin via 64-bit
// (dist_bits<<32 | j) warp butterfly min — exactly reproduces the reference's
// unfused-fp32 dist and first-occurrence (smallest j) tie-break.
//
// Output layout (float32, reference return order):
//   [0 .. BN*8*3)             grouped_xyz   [B,N,8,3]
//   [.. +BN*8*(3+C))          grouped_points[B,N,8,3+C]
//   [.. +BN*8)                idx (int32 cast to float) [B,N,8]
// ---------------------------------------------------------------------------

#define GRIDR   10
#define NCELL   (GRIDR*GRIDR*GRIDR)   // 1000
#define BMAX    2
#define NMAX    4096
#define PRADIUS 0.1f

__device__ int    g_count [BMAX * NCELL];
__device__ int    g_start [BMAX * (NCELL + 1)];
__device__ int    g_cursor[BMAX * NCELL];
__device__ float4 g_sorted[BMAX * NMAX];          // x,y,z, w=bitcast(orig index)
__device__ int    g_bidx  [BMAX * NMAX * 8];

__device__ __forceinline__ int cell_of(float x, float y, float z) {
    int cx = (int)(x * 10.0f); cx = min(max(cx, 0), GRIDR - 1);
    int cy = (int)(y * 10.0f); cy = min(max(cy, 0), GRIDR - 1);
    int cz = (int)(z * 10.0f); cz = min(max(cz, 0), GRIDR - 1);
    return (cx * GRIDR + cy) * GRIDR + cz;
}

__global__ void k_zero(int n) {
    int t = blockIdx.x * blockDim.x + threadIdx.x;
    if (t < n) g_count[t] = 0;
}

__global__ void k_hist(const float* __restrict__ xyz, int B, int N) {
    int t = blockIdx.x * blockDim.x + threadIdx.x;
    if (t >= B * N) return;
    int b = t / N;
    float x = xyz[3 * t + 0], y = xyz[3 * t + 1], z = xyz[3 * t + 2];
    atomicAdd(&g_count[b * NCELL + cell_of(x, y, z)], 1);
}

// One block per batch; 1024-wide Hillis-Steele inclusive scan over 1000 cells.
__global__ void k_scan() {
    __shared__ int s[1024];
    int b = blockIdx.x;
    int tid = threadIdx.x;
    int v = (tid < NCELL) ? g_count[b * NCELL + tid] : 0;
    s[tid] = v;
    __syncthreads();
    #pragma unroll
    for (int off = 1; off < 1024; off <<= 1) {
        int t = (tid >= off) ? s[tid - off] : 0;
        __syncthreads();
        s[tid] += t;
        __syncthreads();
    }
    if (tid < NCELL) {
        int excl = s[tid] - v;
        g_start [b * (NCELL + 1) + tid] = excl;
        g_cursor[b * NCELL + tid]       = excl;
        if (tid == NCELL - 1)
            g_start[b * (NCELL + 1) + NCELL] = s[tid];
    }
}

__global__ void k_scatter(const float* __restrict__ xyz, int B, int N) {
    int t = blockIdx.x * blockDim.x + threadIdx.x;
    if (t >= B * N) return;
    int b = t / N;
    int i = t - b * N;
    float x = xyz[3 * t + 0], y = xyz[3 * t + 1], z = xyz[3 * t + 2];
    int c = cell_of(x, y, z);
    int pos = atomicAdd(&g_cursor[b * NCELL + c], 1);
    g_sorted[b * NMAX + pos] = make_float4(x, y, z, __int_as_float(i));
}

// One WARP per query point. 9 contiguous candidate spans (3x3 xy-cells, z
// cells contiguous in sorted order), lane-strided; 64-bit key butterfly min.
__global__ void k_query_warp(const float* __restrict__ xyz,
                             float* __restrict__ out_idx_f,
                             int B, int N) {
    int w    = (blockIdx.x * blockDim.x + threadIdx.x) >> 5;
    int lane = threadIdx.x & 31;
    if (w >= B * N) return;
    int b = w / N;
    int i = w - b * N;

    const float* xb = xyz + (size_t)b * N * 3;
    float xi = xb[3 * i + 0], yi = xb[3 * i + 1], zi = xb[3 * i + 2];

    // key = (dist_bits << 32) | j ; dist >= 0 so uint order == float order.
    unsigned long long key[8];
    const unsigned long long initk =
        ((unsigned long long)0x7F7FFFFFull << 32) | (unsigned)i;  // FLT_MAX
    #pragma unroll
    for (int o = 0; o < 8; o++) key[o] = initk;

    int cx = min(max((int)(xi * 10.0f), 0), GRIDR - 1);
    int cy = min(max((int)(yi * 10.0f), 0), GRIDR - 1);
    int cz = min(max((int)(zi * 10.0f), 0), GRIDR - 1);
    int ax0 = max(cx - 1, 0), ax1 = min(cx + 1, GRIDR - 1);
    int ay0 = max(cy - 1, 0), ay1 = min(cy + 1, GRIDR - 1);
    int az0 = max(cz - 1, 0), az1 = min(cz + 1, GRIDR - 1);

    const int sbase = b * (NCELL + 1);
    const float4* __restrict__ srt = g_sorted + (size_t)b * NMAX;

    for (int ax = ax0; ax <= ax1; ++ax) {
        for (int ay = ay0; ay <= ay1; ++ay) {
            int rowc = (ax * GRIDR + ay) * GRIDR;
            int s0 = g_start[sbase + rowc + az0];
            int e0 = g_start[sbase + rowc + az1 + 1];
            for (int k = s0 + lane; k < e0; k += 32) {
                float4 p = srt[k];
                float dx = p.x - xi;
                float dy = p.y - yi;
                float dz = p.z - zi;
                if (fabsf(dx) < PRADIUS && fabsf(dy) < PRADIUS &&
                    fabsf(dz) < PRADIUS) {
                    unsigned j = (unsigned)__float_as_int(p.w);
                    float d = __fadd_rn(
                        __fadd_rn(__fmul_rn(dx, dx), __fmul_rn(dy, dy)),
                        __fmul_rn(dz, dz));
                    unsigned long long ck =
                        ((unsigned long long)(unsigned)__float_as_int(d) << 32) | j;
                    int oct = ((dx > 0.0f) ? 4 : 0) |
                              ((dy > 0.0f) ? 2 : 0) |
                              ((dz > 0.0f) ? 1 : 0);
                    #pragma unroll
                    for (int o = 0; o < 8; o++)
                        if (oct == o && ck < key[o]) key[o] = ck;
                }
            }
        }
    }

    // Butterfly min-reduce all 8 octant keys across the warp.
    #pragma unroll
    for (int off = 16; off > 0; off >>= 1) {
        #pragma unroll
        for (int o = 0; o < 8; o++) {
            unsigned long long other =
                __shfl_xor_sync(0xFFFFFFFFu, key[o], off);
            if (other < key[o]) key[o] = other;
        }
    }

    if (lane < 8) {
        int j = (int)(unsigned)(key[lane] & 0xFFFFFFFFull);
        g_bidx[(size_t)w * 8 + lane]    = j;
        out_idx_f[(size_t)w * 8 + lane] = (float)j;
    }
}

// One warp per (b,i,o) group: 3 centered coords + C gathered features.
__global__ void k_gather(const float* __restrict__ xyz,
                         const float* __restrict__ pts,
                         float* __restrict__ gxyz,
                         float* __restrict__ gp,
                         int B, int N, int C) {
    int warps_per_blk = blockDim.x >> 5;
    int g = blockIdx.x * warps_per_blk + (threadIdx.x >> 5);
    int total = B * N * 8;
    if (g >= total) return;
    int lane = threadIdx.x & 31;

    int jj  = g_bidx[g];
    int b   = g / (N * 8);
    int loc = g - b * N * 8;
    int i   = loc >> 3;

    const float* xb = xyz + (size_t)b * N * 3;
    const float* pb = pts + (size_t)b * N * C;
    int F = 3 + C;

    for (int c = lane; c < F; c += 32) {
        float v;
        if (c < 3) v = xb[jj * 3 + c] - xb[i * 3 + c];
        else       v = pb[(size_t)jj * C + (c - 3)];
        gp[(size_t)g * F + c] = v;
        if (c < 3) gxyz[(size_t)g * 3 + c] = v;
    }
}

extern "C" void kernel_launch(void* const* d_in, const int* in_sizes, int n_in,
                              void* d_out, int out_size) {
    const float* xyz = (const float*)d_in[0];
    const float* pts = (const float*)d_in[1];
    float* out = (float*)d_out;

    int BN = in_sizes[0] / 3;       // B*N = 8192
    int B  = 2;
    int N  = BN / B;                // 4096
    int C  = in_sizes[1] / BN;      // 64

    size_t nG = (size_t)BN * 8;
    float* gxyz  = out;
    float* gp    = out + nG * 3;
    float* idx_f = out + nG * 3 + nG * (size_t)(3 + C);

    k_zero      <<<(B * NCELL + 255) / 256, 256>>>(B * NCELL);
    k_hist      <<<(BN + 255) / 256, 256>>>(xyz, B, N);
    k_scan      <<<B, 1024>>>();
    k_scatter   <<<(BN + 255) / 256, 256>>>(xyz, B, N);
    k_query_warp<<<(BN * 32 + 255) / 256, 256>>>(xyz, idx_f, B, N);
    k_gather    <<<(int)((nG + 7) / 8), 256>>>(xyz, pts, gxyz, gp, B, N, C);
}

// round 5
// speedup vs baseline: 3.0306x; 1.2574x over previous
#include <cuda_runtime.h>
#include <float.h>

// ---------------------------------------------------------------------------
// PointSIFT select_cube + group, fused 2-kernel pipeline.
//   k_build       : per-batch block -> smem histogram + scan + scatter
//                   (counting sort on 10^3 grid, cell size == radius)
//   k_query_gather: warp-per-query octant NN search (9 contiguous spans,
//                   64-bit (dist,j) butterfly min) + fused gather/write.
//
// Output layout (float32, reference return order):
//   [0 .. BN*8*3)             grouped_xyz   [B,N,8,3]
//   [.. +BN*8*(3+C))          grouped_points[B,N,8,3+C]
//   [.. +BN*8)                idx (int32 cast to float) [B,N,8]
// ---------------------------------------------------------------------------

#define GRIDR   10
#define NCELL   (GRIDR*GRIDR*GRIDR)   // 1000
#define BMAX    2
#define NMAX    4096
#define PRADIUS 0.1f

__device__ int    g_start [BMAX * (NCELL + 1)];
__device__ float4 g_sorted[BMAX * NMAX];   // x,y,z, w = bitcast(orig index)

__device__ __forceinline__ int cell_of(float x, float y, float z) {
    int cx = (int)(x * 10.0f); cx = min(max(cx, 0), GRIDR - 1);
    int cy = (int)(y * 10.0f); cy = min(max(cy, 0), GRIDR - 1);
    int cz = (int)(z * 10.0f); cz = min(max(cz, 0), GRIDR - 1);
    return (cx * GRIDR + cy) * GRIDR + cz;
}

// One block per batch. Histogram + scan + scatter entirely via shared memory.
__global__ __launch_bounds__(1024) void k_build(const float* __restrict__ xyz,
                                                int N) {
    __shared__ int s_scan[1024];     // scan workspace
    __shared__ int s_cur [NCELL];    // per-cell cursor (excl. prefix)

    int b   = blockIdx.x;
    int tid = threadIdx.x;
    const float* xb = xyz + (size_t)b * N * 3;

    // zero histogram (reuse s_cur as histogram first)
    if (tid < NCELL) s_cur[tid] = 0;
    __syncthreads();

    // load up to 4 points/thread, histogram with smem atomics
    const int PT = (NMAX + 1023) / 1024;   // 4
    float px[PT], py[PT], pz[PT];
    int   pc[PT];
    #pragma unroll
    for (int p = 0; p < PT; p++) {
        int i = tid + p * 1024;
        pc[p] = -1;
        if (i < N) {
            px[p] = xb[3 * i + 0];
            py[p] = xb[3 * i + 1];
            pz[p] = xb[3 * i + 2];
            pc[p] = cell_of(px[p], py[p], pz[p]);
            atomicAdd(&s_cur[pc[p]], 1);
        }
    }
    __syncthreads();

    // inclusive Hillis-Steele scan of the 1000 counts
    int v = (tid < NCELL) ? s_cur[tid] : 0;
    s_scan[tid] = v;
    __syncthreads();
    #pragma unroll
    for (int off = 1; off < 1024; off <<= 1) {
        int t = (tid >= off) ? s_scan[tid - off] : 0;
        __syncthreads();
        s_scan[tid] += t;
        __syncthreads();
    }
    if (tid < NCELL) {
        int excl = s_scan[tid] - v;
        g_start[b * (NCELL + 1) + tid] = excl;
        s_cur[tid] = excl;
        if (tid == NCELL - 1)
            g_start[b * (NCELL + 1) + NCELL] = s_scan[tid];
    }
    __syncthreads();

    // scatter (smem cursor atomics, coalesced-ish float4 stores)
    float4* dst = g_sorted + (size_t)b * NMAX;
    #pragma unroll
    for (int p = 0; p < PT; p++) {
        if (pc[p] >= 0) {
            int pos = atomicAdd(&s_cur[pc[p]], 1);
            int i = tid + p * 1024;
            dst[pos] = make_float4(px[p], py[p], pz[p], __int_as_float(i));
        }
    }
}

// One WARP per query: octant NN search + fused gather.
__global__ void k_query_gather(const float* __restrict__ xyz,
                               const float* __restrict__ pts,
                               float* __restrict__ gxyz,
                               float* __restrict__ gp,
                               float* __restrict__ idx_f,
                               int B, int N, int C) {
    int w    = (blockIdx.x * blockDim.x + threadIdx.x) >> 5;
    int lane = threadIdx.x & 31;
    if (w >= B * N) return;
    int b = w / N;
    int i = w - b * N;

    const float* xb = xyz + (size_t)b * N * 3;
    float xi = xb[3 * i + 0], yi = xb[3 * i + 1], zi = xb[3 * i + 2];

    // key = (dist_bits << 32) | j ; dist >= 0 so uint order == float order.
    unsigned long long key[8];
    const unsigned long long initk =
        ((unsigned long long)0x7F7FFFFFull << 32) | (unsigned)i;  // FLT_MAX
    #pragma unroll
    for (int o = 0; o < 8; o++) key[o] = initk;

    int cx = min(max((int)(xi * 10.0f), 0), GRIDR - 1);
    int cy = min(max((int)(yi * 10.0f), 0), GRIDR - 1);
    int cz = min(max((int)(zi * 10.0f), 0), GRIDR - 1);
    int ax0 = max(cx - 1, 0), ax1 = min(cx + 1, GRIDR - 1);
    int ay0 = max(cy - 1, 0), ay1 = min(cy + 1, GRIDR - 1);
    int az0 = max(cz - 1, 0), az1 = min(cz + 1, GRIDR - 1);

    const int sbase = b * (NCELL + 1);
    const float4* __restrict__ srt = g_sorted + (size_t)b * NMAX;

    for (int ax = ax0; ax <= ax1; ++ax) {
        for (int ay = ay0; ay <= ay1; ++ay) {
            int rowc = (ax * GRIDR + ay) * GRIDR;
            int s0 = g_start[sbase + rowc + az0];
            int e0 = g_start[sbase + rowc + az1 + 1];
            for (int k = s0 + lane; k < e0; k += 32) {
                float4 p = srt[k];
                float dx = p.x - xi;
                float dy = p.y - yi;
                float dz = p.z - zi;
                if (fabsf(dx) < PRADIUS && fabsf(dy) < PRADIUS &&
                    fabsf(dz) < PRADIUS) {
                    unsigned j = (unsigned)__float_as_int(p.w);
                    float d = __fadd_rn(
                        __fadd_rn(__fmul_rn(dx, dx), __fmul_rn(dy, dy)),
                        __fmul_rn(dz, dz));
                    unsigned long long ck =
                        ((unsigned long long)(unsigned)__float_as_int(d) << 32) | j;
                    int oct = ((dx > 0.0f) ? 4 : 0) |
                              ((dy > 0.0f) ? 2 : 0) |
                              ((dz > 0.0f) ? 1 : 0);
                    #pragma unroll
                    for (int o = 0; o < 8; o++)
                        if (oct == o && ck < key[o]) key[o] = ck;
                }
            }
        }
    }

    // butterfly min-reduce (all lanes end with the winner)
    #pragma unroll
    for (int off = 16; off > 0; off >>= 1) {
        #pragma unroll
        for (int o = 0; o < 8; o++) {
            unsigned long long other =
                __shfl_xor_sync(0xFFFFFFFFu, key[o], off);
            if (other < key[o]) key[o] = other;
        }
    }

    if (lane < 8)
        idx_f[(size_t)w * 8 + lane] =
            (float)(int)(unsigned)(key[lane] & 0xFFFFFFFFull);

    // fused gather: 8 octants x (3 centered coords + C features)
    const float* pb = pts + (size_t)b * N * C;
    const int F = 3 + C;   // 67
    #pragma unroll
    for (int o = 0; o < 8; o++) {
        int jj = (int)(unsigned)(key[o] & 0xFFFFFFFFull);   // uniform in warp
        size_t g = (size_t)w * 8 + o;
        for (int c = lane; c < F; c += 32) {
            float vv;
            if (c < 3) vv = xb[jj * 3 + c] - xb[i * 3 + c];
            else       vv = pb[(size_t)jj * C + (c - 3)];
            gp[g * F + c] = vv;
            if (c < 3) gxyz[g * 3 + c] = vv;
        }
    }
}

extern "C" void kernel_launch(void* const* d_in, const int* in_sizes, int n_in,
                              void* d_out, int out_size) {
    const float* xyz = (const float*)d_in[0];
    const float* pts = (const float*)d_in[1];
    float* out = (float*)d_out;

    int BN = in_sizes[0] / 3;       // B*N = 8192
    int B  = 2;
    int N  = BN / B;                // 4096
    int C  = in_sizes[1] / BN;      // 64

    size_t nG = (size_t)BN * 8;
    float* gxyz  = out;
    float* gp    = out + nG * 3;
    float* idx_f = out + nG * 3 + nG * (size_t)(3 + C);

    k_build<<<B, 1024>>>(xyz, N);
    k_query_gather<<<(BN * 32 + 255) / 256, 256>>>(
        xyz, pts, gxyz, gp, idx_f, B, N, C);
}

// round 6
// speedup vs baseline: 4.1966x; 1.3847x over previous
#include <cuda_runtime.h>
#include <float.h>

// ---------------------------------------------------------------------------
// PointSIFT select_cube + group, fused 2-kernel pipeline.
//   k_build       : per-batch block -> smem histogram + scan + scatter
//                   (counting sort on 10^3 grid, cell size == radius)
//   k_query_gather: warp-per-query octant NN search. Per-candidate winner
//                   selection via ONE smem atomicMin on a 64-bit
//                   (dist_bits<<32 | j) key (replaces 8-way compare chain +
//                   shuffle butterfly). Gather is float4-vectorized through
//                   an smem staging buffer.
//
// Output layout (float32, reference return order):
//   [0 .. BN*8*3)             grouped_xyz   [B,N,8,3]
//   [.. +BN*8*(3+C))          grouped_points[B,N,8,3+C]
//   [.. +BN*8)                idx (int32 cast to float) [B,N,8]
// ---------------------------------------------------------------------------

#define GRIDR   10
#define NCELL   (GRIDR*GRIDR*GRIDR)   // 1000
#define BMAX    2
#define NMAX    4096
#define PRADIUS 0.1f
#define WPB     8                     // warps per block in query kernel

__device__ int    g_start [BMAX * (NCELL + 1)];
__device__ float4 g_sorted[BMAX * NMAX];   // x,y,z, w = bitcast(orig index)

__device__ __forceinline__ int cell_of(float x, float y, float z) {
    int cx = (int)(x * 10.0f); cx = min(max(cx, 0), GRIDR - 1);
    int cy = (int)(y * 10.0f); cy = min(max(cy, 0), GRIDR - 1);
    int cz = (int)(z * 10.0f); cz = min(max(cz, 0), GRIDR - 1);
    return (cx * GRIDR + cy) * GRIDR + cz;
}

// One block per batch. Histogram + scan + scatter entirely via shared memory.
__global__ __launch_bounds__(1024) void k_build(const float* __restrict__ xyz,
                                                int N) {
    __shared__ int s_scan[1024];
    __shared__ int s_cur [NCELL];

    int b   = blockIdx.x;
    int tid = threadIdx.x;
    const float* xb = xyz + (size_t)b * N * 3;

    if (tid < NCELL) s_cur[tid] = 0;
    __syncthreads();

    const int PT = (NMAX + 1023) / 1024;   // 4
    float px[PT], py[PT], pz[PT];
    int   pc[PT];
    #pragma unroll
    for (int p = 0; p < PT; p++) {
        int i = tid + p * 1024;
        pc[p] = -1;
        if (i < N) {
            px[p] = xb[3 * i + 0];
            py[p] = xb[3 * i + 1];
            pz[p] = xb[3 * i + 2];
            pc[p] = cell_of(px[p], py[p], pz[p]);
            atomicAdd(&s_cur[pc[p]], 1);
        }
    }
    __syncthreads();

    int v = (tid < NCELL) ? s_cur[tid] : 0;
    s_scan[tid] = v;
    __syncthreads();
    #pragma unroll
    for (int off = 1; off < 1024; off <<= 1) {
        int t = (tid >= off) ? s_scan[tid - off] : 0;
        __syncthreads();
        s_scan[tid] += t;
        __syncthreads();
    }
    if (tid < NCELL) {
        int excl = s_scan[tid] - v;
        g_start[b * (NCELL + 1) + tid] = excl;
        s_cur[tid] = excl;
        if (tid == NCELL - 1)
            g_start[b * (NCELL + 1) + NCELL] = s_scan[tid];
    }
    __syncthreads();

    float4* dst = g_sorted + (size_t)b * NMAX;
    #pragma unroll
    for (int p = 0; p < PT; p++) {
        if (pc[p] >= 0) {
            int pos = atomicAdd(&s_cur[pc[p]], 1);
            int i = tid + p * 1024;
            dst[pos] = make_float4(px[p], py[p], pz[p], __int_as_float(i));
        }
    }
}

// One WARP per query point.
__global__ __launch_bounds__(WPB * 32)
void k_query_gather(const float* __restrict__ xyz,
                    const float* __restrict__ pts,
                    float* __restrict__ gxyz,
                    float* __restrict__ gp,
                    float* __restrict__ idx_f,
                    int B, int N, int C) {
    __shared__ alignas(16) float               s_stage[WPB][536]; // gp rows
    __shared__ alignas(16) float               s_gx   [WPB][24];  // gxyz rows
    __shared__ unsigned long long              s_key  [WPB][8];
    __shared__ int                             s_jj   [WPB][8];

    int wl   = threadIdx.x >> 5;
    int lane = threadIdx.x & 31;
    int w    = blockIdx.x * WPB + wl;
    if (w >= B * N) return;
    int b = w / N;
    int i = w - b * N;

    const float* xb = xyz + (size_t)b * N * 3;
    float xi = xb[3 * i + 0], yi = xb[3 * i + 1], zi = xb[3 * i + 2];

    // key = (dist_bits << 32) | j ; dist >= 0 so uint order == float order.
    if (lane < 8)
        s_key[wl][lane] =
            ((unsigned long long)0x7F7FFFFFull << 32) | (unsigned)i; // FLT_MAX
    __syncwarp();

    int cx = min(max((int)(xi * 10.0f), 0), GRIDR - 1);
    int cy = min(max((int)(yi * 10.0f), 0), GRIDR - 1);
    int cz = min(max((int)(zi * 10.0f), 0), GRIDR - 1);
    int ax0 = max(cx - 1, 0), ax1 = min(cx + 1, GRIDR - 1);
    int ay0 = max(cy - 1, 0), ay1 = min(cy + 1, GRIDR - 1);
    int az0 = max(cz - 1, 0), az1 = min(cz + 1, GRIDR - 1);

    const int sbase = b * (NCELL + 1);
    const float4* __restrict__ srt = g_sorted + (size_t)b * NMAX;

    for (int ax = ax0; ax <= ax1; ++ax) {
        for (int ay = ay0; ay <= ay1; ++ay) {
            int rowc = (ax * GRIDR + ay) * GRIDR;
            int s0 = g_start[sbase + rowc + az0];
            int e0 = g_start[sbase + rowc + az1 + 1];
            for (int k = s0 + lane; k < e0; k += 32) {
                float4 p = srt[k];
                float dx = p.x - xi;
                float dy = p.y - yi;
                float dz = p.z - zi;
                if (fabsf(dx) < PRADIUS && fabsf(dy) < PRADIUS &&
                    fabsf(dz) < PRADIUS) {
                    unsigned j = (unsigned)__float_as_int(p.w);
                    float d = __fadd_rn(
                        __fadd_rn(__fmul_rn(dx, dx), __fmul_rn(dy, dy)),
                        __fmul_rn(dz, dz));
                    unsigned long long ck =
                        ((unsigned long long)(unsigned)__float_as_int(d) << 32) | j;
                    int oct = ((dx > 0.0f) ? 4 : 0) |
                              ((dy > 0.0f) ? 2 : 0) |
                              ((dz > 0.0f) ? 1 : 0);
                    atomicMin(&s_key[wl][oct], ck);
                }
            }
        }
    }
    __syncwarp();

    // publish winners: idx output + int table for the gather
    if (lane < 8) {
        int j = (int)(unsigned)(s_key[wl][lane] & 0xFFFFFFFFull);
        s_jj[wl][lane] = j;
        idx_f[(size_t)w * 8 + lane] = (float)j;
    }
    __syncwarp();

    // centered xyz: 24 values, lanes 0..23 -> stage both gp rows and gxyz
    if (lane < 24) {
        int o = lane / 3;
        int c = lane - o * 3;
        int jj = s_jj[wl][o];
        float v = xb[3 * jj + c] - xb[3 * i + c];
        s_stage[wl][o * 67 + c] = v;
        s_gx[wl][lane] = v;
    }

    // features: 8 octants x 16 float4 = 128 vector loads, 4 full iterations
    const float4* __restrict__ pb4 =
        (const float4*)(pts + (size_t)b * N * C);
    #pragma unroll
    for (int t0 = 0; t0 < 4; t0++) {
        int t  = lane + t0 * 32;
        int o  = t >> 4;
        int q  = t & 15;
        int jj = s_jj[wl][o];
        float4 f4 = pb4[(size_t)jj * 16 + q];
        int base = o * 67 + 3 + q * 4;
        s_stage[wl][base + 0] = f4.x;
        s_stage[wl][base + 1] = f4.y;
        s_stage[wl][base + 2] = f4.z;
        s_stage[wl][base + 3] = f4.w;
    }
    __syncwarp();

    // vectorized write-out: 536 floats = 134 float4 (16B-aligned rows)
    float4*       gpo = (float4*)(gp + (size_t)w * 536);
    const float4* st4 = (const float4*)s_stage[wl];
    #pragma unroll
    for (int f = lane; f < 134; f += 32)
        gpo[f] = st4[f];
    if (lane < 6)
        ((float4*)(gxyz + (size_t)w * 24))[lane] =
            ((const float4*)s_gx[wl])[lane];
}

extern "C" void kernel_launch(void* const* d_in, const int* in_sizes, int n_in,
                              void* d_out, int out_size) {
    const float* xyz = (const float*)d_in[0];
    const float* pts = (const float*)d_in[1];
    float* out = (float*)d_out;

    int BN = in_sizes[0] / 3;       // B*N = 8192
    int B  = 2;
    int N  = BN / B;                // 4096
    int C  = in_sizes[1] / BN;      // 64

    size_t nG = (size_t)BN * 8;
    float* gxyz  = out;
    float* gp    = out + nG * 3;
    float* idx_f = out + nG * 3 + nG * (size_t)(3 + C);

    k_build<<<B, 1024>>>(xyz, N);
    k_query_gather<<<(BN + WPB - 1) / WPB, WPB * 32>>>(
        xyz, pts, gxyz, gp, idx_f, B, N, C);
}

// round 7
// speedup vs baseline: 4.5298x; 1.0794x over previous
#include <cuda_runtime.h>
#include <float.h>

// ---------------------------------------------------------------------------
// PointSIFT select_cube + group, fused 2-kernel pipeline.
//   k_build: per-batch block; smem histogram + warp-shuffle scan + scatter
//            (counting sort on 10^3 grid, cell size == radius).
//   k_query_gather: TWO queries per warp (16-lane sub-warps). Per sub-warp:
//            prefetch 9 span ranges (3x3 xy-cells, z contiguous), stride
//            candidates over 16 lanes, winner via smem atomicMin on a 64-bit
//            (dist_bits<<32 | j) key. Gather staged in smem, written out
//            full-warp coalesced (two adjacent output rows per warp).
//
// Output layout (float32, reference return order):
//   [0 .. BN*8*3)             grouped_xyz   [B,N,8,3]
//   [.. +BN*8*(3+C))          grouped_points[B,N,8,3+C]
//   [.. +BN*8)                idx (int32 cast to float) [B,N,8]
// ---------------------------------------------------------------------------

#define GRIDR   10
#define NCELL   (GRIDR*GRIDR*GRIDR)   // 1000
#define BMAX    2
#define NMAX    4096
#define PRADIUS 0.1f
#define WPB     8                     // warps per block (query kernel)

__device__ int    g_start [BMAX * (NCELL + 1)];
__device__ float4 g_sorted[BMAX * NMAX];   // x,y,z, w = bitcast(orig index)

__device__ __forceinline__ int cell_of(float x, float y, float z) {
    int cx = (int)(x * 10.0f); cx = min(max(cx, 0), GRIDR - 1);
    int cy = (int)(y * 10.0f); cy = min(max(cy, 0), GRIDR - 1);
    int cz = (int)(z * 10.0f); cz = min(max(cz, 0), GRIDR - 1);
    return (cx * GRIDR + cy) * GRIDR + cz;
}

// One block per batch. Histogram + warp-shuffle scan + scatter via smem.
__global__ __launch_bounds__(1024) void k_build(const float* __restrict__ xyz,
                                                int N) {
    __shared__ int s_cur [NCELL];
    __shared__ int s_wsum[32];

    int b    = blockIdx.x;
    int tid  = threadIdx.x;
    int wid  = tid >> 5;
    int lid  = tid & 31;
    const float* xb = xyz + (size_t)b * N * 3;

    if (tid < NCELL) s_cur[tid] = 0;
    __syncthreads();

    const int PT = (NMAX + 1023) / 1024;   // 4
    float px[PT], py[PT], pz[PT];
    int   pc[PT];
    #pragma unroll
    for (int p = 0; p < PT; p++) {
        int i = tid + p * 1024;
        pc[p] = -1;
        if (i < N) {
            px[p] = xb[3 * i + 0];
            py[p] = xb[3 * i + 1];
            pz[p] = xb[3 * i + 2];
            pc[p] = cell_of(px[p], py[p], pz[p]);
            atomicAdd(&s_cur[pc[p]], 1);
        }
    }
    __syncthreads();

    // inclusive scan of 1000 counts: warp shuffle scan + cross-warp pass
    int v = (tid < NCELL) ? s_cur[tid] : 0;
    int x = v;
    #pragma unroll
    for (int off = 1; off < 32; off <<= 1) {
        int y = __shfl_up_sync(0xFFFFFFFFu, x, off);
        if (lid >= off) x += y;
    }
    if (lid == 31) s_wsum[wid] = x;
    __syncthreads();
    if (wid == 0) {
        int y = s_wsum[lid];
        #pragma unroll
        for (int off = 1; off < 32; off <<= 1) {
            int z2 = __shfl_up_sync(0xFFFFFFFFu, y, off);
            if (lid >= off) y += z2;
        }
        s_wsum[lid] = y;
    }
    __syncthreads();
    int incl = x + (wid > 0 ? s_wsum[wid - 1] : 0);
    if (tid < NCELL) {
        int excl = incl - v;
        g_start[b * (NCELL + 1) + tid] = excl;
        s_cur[tid] = excl;
        if (tid == NCELL - 1)
            g_start[b * (NCELL + 1) + NCELL] = incl;
    }
    __syncthreads();

    float4* dst = g_sorted + (size_t)b * NMAX;
    #pragma unroll
    for (int p = 0; p < PT; p++) {
        if (pc[p] >= 0) {
            int pos = atomicAdd(&s_cur[pc[p]], 1);
            int i = tid + p * 1024;
            dst[pos] = make_float4(px[p], py[p], pz[p], __int_as_float(i));
        }
    }
}

// Two queries per warp; 16-lane sub-warp per query.
__global__ __launch_bounds__(WPB * 32)
void k_query_gather(const float* __restrict__ xyz,
                    const float* __restrict__ pts,
                    float* __restrict__ gxyz,
                    float* __restrict__ gp,
                    float* __restrict__ idx_f,
                    int B, int N, int C) {
    __shared__ alignas(16) float  s_stage[WPB][2][536];
    __shared__ alignas(16) float  s_gx   [WPB][2][24];
    __shared__ unsigned long long s_key  [WPB][2][8];
    __shared__ int                s_jj   [WPB][2][8];

    int wl     = threadIdx.x >> 5;
    int lane   = threadIdx.x & 31;
    int sub    = lane >> 4;            // which query of the pair
    int lane16 = lane & 15;
    int w0     = blockIdx.x * (2 * WPB) + 2 * wl;   // first query of warp
    if (w0 >= B * N) return;
    int w = w0 + sub;                  // this sub-warp's query
    int b = w / N;
    int i = w - b * N;

    // init winner keys: key = (dist_bits<<32) | j, seeded with (FLT_MAX, i)
    if (lane < 16) {
        int ss = lane >> 3;
        int ww = w0 + ss;
        int ii = ww - (ww / N) * N;
        s_key[wl][ss][lane & 7] =
            ((unsigned long long)0x7F7FFFFFull << 32) | (unsigned)ii;
    }
    __syncwarp();

    const float* xb = xyz + (size_t)b * N * 3;
    float xi = xb[3 * i + 0], yi = xb[3 * i + 1], zi = xb[3 * i + 2];

    int cx = min(max((int)(xi * 10.0f), 0), GRIDR - 1);
    int cy = min(max((int)(yi * 10.0f), 0), GRIDR - 1);
    int cz = min(max((int)(zi * 10.0f), 0), GRIDR - 1);
    int ax0 = max(cx - 1, 0), ax1 = min(cx + 1, GRIDR - 1);
    int ay0 = max(cy - 1, 0), ay1 = min(cy + 1, GRIDR - 1);
    int az0 = max(cz - 1, 0), az1 = min(cz + 1, GRIDR - 1);
    int nx = ax1 - ax0 + 1, ny = ay1 - ay0 + 1;
    int ns = nx * ny;                       // 4..9 spans

    const unsigned hm = 0xFFFFu << (sub * 16);
    const int sbase = b * (NCELL + 1);
    const float4* __restrict__ srt = g_sorted + (size_t)b * NMAX;

    // prefetch all span ranges in parallel (lanes 0..ns-1 of each half)
    int rs = 0, re = 0;
    if (lane16 < ns) {
        int axx = ax0 + lane16 / ny;
        int ayy = ay0 + lane16 - (lane16 / ny) * ny;
        int rowc = (axx * GRIDR + ayy) * GRIDR;
        rs = g_start[sbase + rowc + az0];
        re = g_start[sbase + rowc + az1 + 1];
    }

    for (int sp = 0; sp < ns; sp++) {
        int s0 = __shfl_sync(hm, rs, sp, 16);
        int e0 = __shfl_sync(hm, re, sp, 16);
        for (int k = s0 + lane16; k < e0; k += 16) {
            float4 p = srt[k];
            float dx = p.x - xi;
            float dy = p.y - yi;
            float dz = p.z - zi;
            if (fabsf(dx) < PRADIUS && fabsf(dy) < PRADIUS &&
                fabsf(dz) < PRADIUS) {
                unsigned j = (unsigned)__float_as_int(p.w);
                float d = __fadd_rn(
                    __fadd_rn(__fmul_rn(dx, dx), __fmul_rn(dy, dy)),
                    __fmul_rn(dz, dz));
                unsigned long long ck =
                    ((unsigned long long)(unsigned)__float_as_int(d) << 32) | j;
                int oct = ((dx > 0.0f) ? 4 : 0) |
                          ((dy > 0.0f) ? 2 : 0) |
                          ((dz > 0.0f) ? 1 : 0);
                atomicMin(&s_key[wl][sub][oct], ck);
            }
        }
    }
    __syncwarp();

    // publish winners (both queries): idx output is 16 contiguous floats
    if (lane < 16) {
        int ss = lane >> 3;
        int oo = lane & 7;
        int j = (int)(unsigned)(s_key[wl][ss][oo] & 0xFFFFFFFFull);
        s_jj[wl][ss][oo] = j;
        idx_f[(size_t)w0 * 8 + lane] = (float)j;
    }
    __syncwarp();

    // centered xyz: 24 values per query, sub-warp strided
    for (int c3 = lane16; c3 < 24; c3 += 16) {
        int o = c3 / 3;
        int c = c3 - o * 3;
        int jj = s_jj[wl][sub][o];
        float vv = xb[3 * jj + c] - xb[3 * i + c];
        s_stage[wl][sub][o * 67 + c] = vv;
        s_gx[wl][sub][c3] = vv;
    }

    // features: 8 octants x 16 float4 per query, sub-warp strided
    const float4* __restrict__ pb4 = (const float4*)(pts + (size_t)b * N * C);
    #pragma unroll
    for (int t0 = 0; t0 < 8; t0++) {
        int t  = lane16 + t0 * 16;      // 0..127
        int o  = t >> 4;
        int q  = t & 15;
        int jj = s_jj[wl][sub][o];
        float4 f4 = pb4[(size_t)jj * 16 + q];
        int base = o * 67 + 3 + q * 4;
        s_stage[wl][sub][base + 0] = f4.x;
        s_stage[wl][sub][base + 1] = f4.y;
        s_stage[wl][sub][base + 2] = f4.z;
        s_stage[wl][sub][base + 3] = f4.w;
    }
    __syncwarp();

    // full-warp coalesced write-out of BOTH adjacent rows:
    // gp: 2 x 536 floats = 268 float4 contiguous at gp + w0*536
    float4*       gpo = (float4*)(gp + (size_t)w0 * 536);
    const float4* st4 = (const float4*)&s_stage[wl][0][0];
    #pragma unroll
    for (int f = lane; f < 268; f += 32)
        gpo[f] = st4[f];
    // gxyz: 2 x 24 floats = 12 float4 contiguous at gxyz + w0*24
    if (lane < 12)
        ((float4*)(gxyz + (size_t)w0 * 24))[lane] =
            ((const float4*)&s_gx[wl][0][0])[lane];
}

extern "C" void kernel_launch(void* const* d_in, const int* in_sizes, int n_in,
                              void* d_out, int out_size) {
    const float* xyz = (const float*)d_in[0];
    const float* pts = (const float*)d_in[1];
    float* out = (float*)d_out;

    int BN = in_sizes[0] / 3;       // B*N = 8192
    int B  = 2;
    int N  = BN / B;                // 4096
    int C  = in_sizes[1] / BN;      // 64

    size_t nG = (size_t)BN * 8;
    float* gxyz  = out;
    float* gp    = out + nG * 3;
    float* idx_f = out + nG * 3 + nG * (size_t)(3 + C);

    k_build<<<B, 1024>>>(xyz, N);
    k_query_gather<<<(BN + 2 * WPB - 1) / (2 * WPB), WPB * 32>>>(
        xyz, pts, gxyz, gp, idx_f, B, N, C);
}